// round 14
// baseline (speedup 1.0000x reference)
#include <cuda_runtime.h>
#include <math.h>

#define Bb 64
#define Nn 1024
#define Hh 64
#define Tt 10

#define NU_BKT 64
#define NU_ENC 1024
#define NU_G   640
#define NU_C   256
#define NU_L   640
#define NU_H   1024

// ---------------- scratch (device globals; permuted row space) -----------------
__device__ __align__(16) float g_nrmP[Bb*Nn*Hh];
__device__ __align__(16) float g_xw0 [Bb*Nn*Hh];
__device__ __align__(16) float g_xw1 [Bb*Nn*Hh];
__device__ __align__(16) float g_h2P [Bb*Nn*Hh];
__device__ __align__(16) float g_G   [Bb*Tt*Hh*Hh];
__device__ __align__(16) float g_M   [Bb*Tt*Hh*Hh];
__device__ int g_pos[Bb*Nn];
__device__ int g_off[Bb*Tt];
__device__ int g_cnt[Bb*Tt];
__device__ __align__(16) float g_ctx[Bb*Hh];
__device__ int      g_bar_count = 0;
__device__ unsigned g_bar_gen   = 0;
__device__ int      g_ticket    = 0;

#define FMA4(A, s, v) { (A).x += (s)*(v).x; (A).y += (s)*(v).y; (A).z += (s)*(v).z; (A).w += (s)*(v).w; }

// grid-wide barrier; nblk CTAs all resident (grid sized from occupancy query).
__device__ __forceinline__ void grid_bar(unsigned& gen, int nblk) {
    __threadfence();
    __syncthreads();
    if (threadIdx.x == 0) {
        if (atomicAdd(&g_bar_count, 1) == nblk - 1) {
            g_ticket = 0;
            g_bar_count = 0;
            __threadfence();
            atomicExch(&g_bar_gen, gen + 1);
        } else {
            while (atomicAdd(&g_bar_gen, 0u) != gen + 1) __nanosleep(64);
        }
    }
    __syncthreads();
    __threadfence();
    gen += 1;
}

#define NEXT(u) { if (tid == 0) s_u = atomicAdd(&g_ticket, 1); \
                  __syncthreads(); u = s_u; __syncthreads(); }

__global__ __launch_bounds__(256, 3) void mega(
    const float* __restrict__ tf,   const int* __restrict__ types,
    const float* __restrict__ prev,
    const float* __restrict__ ew1,  const float* __restrict__ eb1,
    const float* __restrict__ ew2,  const float* __restrict__ eb2,
    const float* __restrict__ cont,
    const float* __restrict__ gw,   const float* __restrict__ gb,
    const float* __restrict__ wih,  const float* __restrict__ whh,
    const float* __restrict__ bih,  const float* __restrict__ bhh,
    const float* __restrict__ hw1,  const float* __restrict__ hb1,
    const float* __restrict__ hw2,  const float* __restrict__ hb2,
    float* __restrict__ out, int nblk)
{
    extern __shared__ __align__(16) float sm[];
    float* SA = sm;            // 4352 floats
    float* SB = sm + 4352;
    float* SC = sm + 8704;
    float* SD = sm + 13056;
    __shared__ int s_u;
    __shared__ unsigned s_gen0;
    __shared__ __align__(16) float s_bias[64];
    __shared__ float s_S[112];
    __shared__ int s_cnt[16];
    __shared__ int s_offs[16];

    const int tid = threadIdx.x;
    const int tx = tid & 15, ty = tid >> 4;

    if (tid == 0) s_gen0 = atomicAdd(&g_bar_gen, 0u);
    __syncthreads();
    unsigned gen = s_gen0;

    // ================= P0: bucket ==============================================
    for (;;) {
        int u; NEXT(u);
        if (u >= NU_BKT) break;
        int b = u;
        if (tid < Tt) s_cnt[tid] = 0;
        if (tid < 64) g_ctx[b*64 + tid] = 0.f;
        __syncthreads();
        int t4[4], r4[4];
        #pragma unroll
        for (int it = 0; it < 4; ++it) {
            int n = it*256 + tid;
            t4[it] = types[b*Nn + n];
            r4[it] = atomicAdd(&s_cnt[t4[it]], 1);
        }
        __syncthreads();
        if (tid == 0) {
            int a = 0;
            #pragma unroll
            for (int i = 0; i < Tt; ++i) { s_offs[i] = a; a += s_cnt[i]; }
        }
        __syncthreads();
        #pragma unroll
        for (int it = 0; it < 4; ++it) {
            int n = it*256 + tid;
            g_pos[b*Nn + n] = b*Nn + s_offs[t4[it]] + r4[it];
        }
        if (tid < Tt) { g_cnt[b*Tt + tid] = s_cnt[tid]; g_off[b*Tt + tid] = s_offs[tid]; }
        __syncthreads();
    }
    grid_bar(gen, nblk);

    // ================= P1: encoder -> nrmP + HW0 ===============================
    {
        // stage weights once: SB = w2^T, SC = W0^T, SD smalls
        #pragma unroll
        for (int it = 0; it < 16; ++it) {
            int e = tid + it*256;
            int j = e >> 6, k = e & 63;
            SB[k*68 + j] = ew2[e];
            SC[(e & 63)*68 + (e >> 6)] = gw[e];
        }
        if (tid < 192) SD[tid] = ew1[tid];
        if (tid < 64)  { SD[192 + tid] = eb1[tid]; SD[256 + tid] = eb2[tid]; }
        __syncthreads();
        for (;;) {
            int u; NEXT(u);
            if (u >= NU_ENC) break;
            int base = u << 6;
            if (tid < 192) SD[320 + tid] = tf[base*3 + tid];
            __syncthreads();
            #pragma unroll
            for (int it = 0; it < 16; ++it) {
                int e = tid + it*256;
                int row = e >> 6, k = e & 63;
                float h = SD[320+row*3+0]*SD[k*3+0] + SD[320+row*3+1]*SD[k*3+1]
                        + SD[320+row*3+2]*SD[k*3+2] + SD[192+k];
                SA[row*68 + k] = fmaxf(h, 0.f);
            }
            __syncthreads();
            float4 acc[4];
            #pragma unroll
            for (int i = 0; i < 4; ++i) acc[i] = make_float4(0.f,0.f,0.f,0.f);
            #pragma unroll 8
            for (int kk = 0; kk < 64; ++kk) {
                float4 bb = *(const float4*)&SB[kk*68 + tx*4];
                float a0 = SA[(ty*4+0)*68 + kk];
                float a1 = SA[(ty*4+1)*68 + kk];
                float a2 = SA[(ty*4+2)*68 + kk];
                float a3 = SA[(ty*4+3)*68 + kk];
                FMA4(acc[0], a0, bb); FMA4(acc[1], a1, bb);
                FMA4(acc[2], a2, bb); FMA4(acc[3], a3, bb);
            }
            int p[4];
            #pragma unroll
            for (int i = 0; i < 4; ++i) {
                acc[i].x += SD[256 + tx*4+0]; acc[i].y += SD[256 + tx*4+1];
                acc[i].z += SD[256 + tx*4+2]; acc[i].w += SD[256 + tx*4+3];
                float sq = acc[i].x*acc[i].x + acc[i].y*acc[i].y
                         + acc[i].z*acc[i].z + acc[i].w*acc[i].w;
                #pragma unroll
                for (int o = 8; o > 0; o >>= 1) sq += __shfl_xor_sync(0xffffffffu, sq, o);
                float inv = 1.f / fmaxf(sqrtf(sq), 1e-12f);
                p[i] = g_pos[base + ty*4 + i];
                float4 nv = make_float4(acc[i].x*inv, acc[i].y*inv, acc[i].z*inv, acc[i].w*inv);
                *(float4*)&g_nrmP[p[i]*64 + tx*4] = nv;
            }
            __syncthreads();
            #pragma unroll
            for (int i = 0; i < 4; ++i)
                *(float4*)&SA[(ty*4+i)*68 + tx*4] = acc[i];
            __syncthreads();
            float4 acc2[4];
            #pragma unroll
            for (int i = 0; i < 4; ++i) acc2[i] = make_float4(0.f,0.f,0.f,0.f);
            #pragma unroll 8
            for (int kk = 0; kk < 64; ++kk) {
                float4 bb = *(const float4*)&SC[kk*68 + tx*4];
                float a0 = SA[(ty*4+0)*68 + kk];
                float a1 = SA[(ty*4+1)*68 + kk];
                float a2 = SA[(ty*4+2)*68 + kk];
                float a3 = SA[(ty*4+3)*68 + kk];
                FMA4(acc2[0], a0, bb); FMA4(acc2[1], a1, bb);
                FMA4(acc2[2], a2, bb); FMA4(acc2[3], a3, bb);
            }
            #pragma unroll
            for (int i = 0; i < 4; ++i)
                *(float4*)&g_xw0[p[i]*64 + tx*4] = acc2[i];
            __syncthreads();
        }
    }
    grid_bar(gen, nblk);

    // ================= layers ===================================================
    for (int l = 0; l < 2; ++l) {
        const float4* nrm4 = (const float4*)g_nrmP;
        const float*  hw   = (l == 0) ? g_xw0 : g_xw1;
        const float4* hw4  = (const float4*)hw;

        // ---- P2: gmat ----
        for (;;) {
            int u; NEXT(u);
            if (u >= NU_G) break;
            int b = u / 10, t = u - b*10;
            int Kt = g_cnt[b*Tt + t];
            int rbase = (b << 10) + g_off[b*Tt + t];
            float4 acc[4];
            #pragma unroll
            for (int i = 0; i < 4; ++i) acc[i] = make_float4(0.f,0.f,0.f,0.f);
            for (int r0 = 0; r0 < Kt; r0 += 64) {
                #pragma unroll
                for (int it = 0; it < 4; ++it) {
                    int e = tid + it*256;
                    int rr = e >> 4, kq = e & 15;
                    int r = r0 + rr;
                    float4 a = make_float4(0.f,0.f,0.f,0.f);
                    float4 w = make_float4(0.f,0.f,0.f,0.f);
                    if (r < Kt) {
                        int gi = (rbase + r)*16 + kq;
                        a = nrm4[gi];
                        w = hw4[gi];
                    }
                    *(float4*)&SA[rr*68 + kq*4] = a;
                    *(float4*)&SB[rr*68 + kq*4] = w;
                }
                __syncthreads();
                #pragma unroll 8
                for (int rr = 0; rr < 64; ++rr) {
                    float4 a  = *(const float4*)&SA[rr*68 + ty*4];
                    float4 bb = *(const float4*)&SB[rr*68 + tx*4];
                    FMA4(acc[0], a.x, bb); FMA4(acc[1], a.y, bb);
                    FMA4(acc[2], a.z, bb); FMA4(acc[3], a.w, bb);
                }
                __syncthreads();
            }
            float* Gp = &g_G[(b*Tt + t)*4096];
            #pragma unroll
            for (int i = 0; i < 4; ++i)
                *(float4*)&Gp[(ty*4 + i)*64 + tx*4] = acc[i];
        }
        grid_bar(gen, nblk);

        // ---- P3: combine ----
        {
            if (tid < Tt*Tt) s_S[tid] = 1.f / (1.f + expf(-cont[tid]));
            __syncthreads();
            for (;;) {
                int u; NEXT(u);
                if (u >= NU_C) break;
                int b = u >> 2, seg = u & 3;
                int i4 = seg*256 + tid;
                const float4* G4 = (const float4*)g_G + (size_t)b*10240;
                float4*       M4 = (float4*)g_M       + (size_t)b*10240;
                float4 g[Tt];
                #pragma unroll
                for (int t = 0; t < Tt; ++t) g[t] = G4[t*1024 + i4];
                #pragma unroll
                for (int tp = 0; tp < Tt; ++tp) {
                    float4 o = make_float4(0.f,0.f,0.f,0.f);
                    #pragma unroll
                    for (int t = 0; t < Tt; ++t) { float s = s_S[tp*Tt + t]; FMA4(o, s, g[t]); }
                    M4[tp*1024 + i4] = o;
                }
            }
        }
        grid_bar(gen, nblk);

        // ---- P4: layer ----
        {
            if (tid < 64) s_bias[tid] = gb[l*64 + tid];
            if (l == 0) {
                const float* Wp = gw + 4096;
                #pragma unroll
                for (int it = 0; it < 16; ++it) {
                    int e = tid + it*256;
                    SC[(e & 63)*68 + (e >> 6)] = Wp[e];   // W1^T
                }
            }
            __syncthreads();
            for (;;) {
                int u; NEXT(u);
                if (u >= NU_L) break;
                int b = u / 10, t = u - b*10;
                int Kt = g_cnt[b*Tt + t];
                if (Kt == 0) continue;
                int rbase = (b << 10) + g_off[b*Tt + t];
                const float4* Mp4 = (const float4*)&g_M[(b*Tt + t)*4096];
                #pragma unroll
                for (int it = 0; it < 4; ++it) {
                    int e = tid + it*256;
                    *(float4*)&SA[(e >> 4)*68 + (e & 15)*4] = Mp4[e];
                }
                float4 psum = make_float4(0.f,0.f,0.f,0.f);
                float4 bias = *(const float4*)&s_bias[tx*4];
                __syncthreads();

                for (int r0 = 0; r0 < Kt; r0 += 64) {
                    #pragma unroll
                    for (int it = 0; it < 16; ++it) {
                        int e = tid + it*256;
                        int rr = e >> 6, k = e & 63;
                        int r = r0 + rr;
                        SB[k*68 + rr] = (r < Kt) ? g_nrmP[(rbase + r)*64 + k] : 0.f;
                    }
                    __syncthreads();

                    float4 acc[4];
                    #pragma unroll
                    for (int i = 0; i < 4; ++i) acc[i] = make_float4(0.f,0.f,0.f,0.f);
                    #pragma unroll 8
                    for (int kk = 0; kk < 64; ++kk) {
                        float4 a  = *(const float4*)&SB[kk*68 + ty*4];
                        float4 bb = *(const float4*)&SA[kk*68 + tx*4];
                        FMA4(acc[0], a.x, bb); FMA4(acc[1], a.y, bb);
                        FMA4(acc[2], a.z, bb); FMA4(acc[3], a.w, bb);
                    }

                    if (l == 0) {
                        #pragma unroll
                        for (int i = 0; i < 4; ++i) {
                            int r = r0 + ty*4 + i;
                            float4 x = acc[i];
                            if (r < Kt) {
                                float4 hv = *(const float4*)&hw[(rbase + r)*64 + tx*4];
                                x.x = fmaxf(x.x + hv.x + bias.x, 0.f);
                                x.y = fmaxf(x.y + hv.y + bias.y, 0.f);
                                x.z = fmaxf(x.z + hv.z + bias.z, 0.f);
                                x.w = fmaxf(x.w + hv.w + bias.w, 0.f);
                            } else {
                                x = make_float4(0.f,0.f,0.f,0.f);
                            }
                            SD[(tx*4+0)*68 + ty*4 + i] = x.x;
                            SD[(tx*4+1)*68 + ty*4 + i] = x.y;
                            SD[(tx*4+2)*68 + ty*4 + i] = x.z;
                            SD[(tx*4+3)*68 + ty*4 + i] = x.w;
                        }
                        __syncthreads();
                        float4 acc2[4];
                        #pragma unroll
                        for (int i = 0; i < 4; ++i) acc2[i] = make_float4(0.f,0.f,0.f,0.f);
                        #pragma unroll 8
                        for (int kk = 0; kk < 64; ++kk) {
                            float4 a  = *(const float4*)&SD[kk*68 + ty*4];
                            float4 bb = *(const float4*)&SC[kk*68 + tx*4];
                            FMA4(acc2[0], a.x, bb); FMA4(acc2[1], a.y, bb);
                            FMA4(acc2[2], a.z, bb); FMA4(acc2[3], a.w, bb);
                        }
                        #pragma unroll
                        for (int i = 0; i < 4; ++i) {
                            int r = r0 + ty*4 + i;
                            if (r < Kt)
                                *(float4*)&g_xw1[(rbase + r)*64 + tx*4] = acc2[i];
                        }
                        __syncthreads();
                    } else {
                        #pragma unroll
                        for (int i = 0; i < 4; ++i) {
                            int r = r0 + ty*4 + i;
                            if (r < Kt) {
                                float4 x = acc[i];
                                float4 hv = *(const float4*)&hw[(rbase + r)*64 + tx*4];
                                x.x = fmaxf(x.x + hv.x + bias.x, 0.f);
                                x.y = fmaxf(x.y + hv.y + bias.y, 0.f);
                                x.z = fmaxf(x.z + hv.z + bias.z, 0.f);
                                x.w = fmaxf(x.w + hv.w + bias.w, 0.f);
                                *(float4*)&g_h2P[(rbase + r)*64 + tx*4] = x;
                                psum.x += x.x; psum.y += x.y; psum.z += x.z; psum.w += x.w;
                            }
                        }
                        __syncthreads();
                    }
                }

                if (l == 1) {     // ctx partials via SC scratch (unused in l=1)
                    *(float4*)&SC[ty*64 + tx*4] = psum;
                    __syncthreads();
                    if (tid < 64) {
                        float s = 0.f;
                        #pragma unroll
                        for (int q = 0; q < 16; ++q) s += SC[q*64 + tid];
                        atomicAdd(&g_ctx[b*64 + tid], s);
                    }
                    __syncthreads();
                }
            }
        }
        grid_bar(gen, nblk);
    }

    // ================= P5: head (+GRU per unit, K=64) ==========================
    {
        // stage once: SB = W1head^T, SC[384..448] = w2
        #pragma unroll
        for (int it = 0; it < 16; ++it) {
            int e = tid + it*256;
            int j = e >> 6, k = e & 63;
            SB[k*68 + j] = hw1[j*96 + k];
        }
        __syncthreads();
        if (tid < 64) SC[384 + tid] = hw2[tid];
        float b2v = hb2[0];
        const float4* h24 = (const float4*)g_h2P;
        int* s_pos = (int*)&SC[448];
        __syncthreads();
        for (;;) {
            int u; NEXT(u);
            if (u >= NU_H) break;
            int base = u << 6;
            int b = u >> 4;
            if (tid < 64)       SC[tid] = g_ctx[b*64 + tid] * (1.f/1024.f);
            else if (tid < 96)  SC[tid] = prev[b*32 + (tid - 64)];
            else if (tid < 160) s_pos[tid - 96] = g_pos[base + (tid - 96)];
            __syncthreads();
            #pragma unroll
            for (int it = 0; it < 4; ++it) {
                int e = tid + it*256;
                int rr = e >> 4, kq = e & 15;
                *(float4*)&SA[rr*68 + kq*4] = h24[s_pos[rr]*16 + kq];
            }
            if (tid < 96) {
                float gi = bih[tid], gh = bhh[tid];
                #pragma unroll 16
                for (int k = 0; k < 64; ++k) gi += SC[k] * wih[tid*64 + k];
                #pragma unroll 16
                for (int k = 0; k < 32; ++k) gh += SC[64 + k] * whh[tid*32 + k];
                SC[96 + tid] = gi; SC[192 + tid] = gh;
            }
            __syncthreads();
            if (tid < 32) {
                float r  = 1.f / (1.f + expf(-(SC[96  + tid] + SC[192 + tid])));
                float z  = 1.f / (1.f + expf(-(SC[128 + tid] + SC[224 + tid])));
                float nn = tanhf(SC[160 + tid] + r * SC[256 + tid]);
                float ns = (1.f - z)*nn + z*SC[64 + tid];
                SC[288 + tid] = ns;
                if ((u & 15) == 0) out[Bb*Nn + b*32 + tid] = ns;
            }
            __syncthreads();
            if (tid < 64) {
                float v = hb1[tid];
                #pragma unroll
                for (int k = 0; k < 32; ++k) v += hw1[tid*96 + 64 + k] * SC[288 + k];
                SC[320 + tid] = v;    // hs
            }
            __syncthreads();

            float4 hs = *(const float4*)&SC[320 + tx*4];
            float4 acc[4] = {hs, hs, hs, hs};
            #pragma unroll 8
            for (int kk = 0; kk < 64; ++kk) {
                float4 bb = *(const float4*)&SB[kk*68 + tx*4];
                float a0 = SA[(ty*4+0)*68 + kk];
                float a1 = SA[(ty*4+1)*68 + kk];
                float a2 = SA[(ty*4+2)*68 + kk];
                float a3 = SA[(ty*4+3)*68 + kk];
                FMA4(acc[0], a0, bb); FMA4(acc[1], a1, bb);
                FMA4(acc[2], a2, bb); FMA4(acc[3], a3, bb);
            }
            float4 w2v = *(const float4*)&SC[384 + tx*4];
            #pragma unroll
            for (int i = 0; i < 4; ++i) {
                float y = fmaxf(acc[i].x, 0.f)*w2v.x + fmaxf(acc[i].y, 0.f)*w2v.y
                        + fmaxf(acc[i].z, 0.f)*w2v.z + fmaxf(acc[i].w, 0.f)*w2v.w;
                #pragma unroll
                for (int o = 8; o > 0; o >>= 1) y += __shfl_xor_sync(0xffffffffu, y, o);
                if (tx == 0) out[base + ty*4 + i] = y + b2v;
            }
            __syncthreads();
        }
    }
    grid_bar(gen, nblk);   // resets ticket for next replay
}

// ---------------- launch ---------------------------------------------------------
extern "C" void kernel_launch(void* const* d_in, const int* in_sizes, int n_in,
                              void* d_out, int out_size)
{
    const float* tf    = (const float*)d_in[0];
    const int*   types = (const int*)  d_in[1];
    const float* prev  = (const float*)d_in[2];
    const float* ew1   = (const float*)d_in[3];
    const float* eb1   = (const float*)d_in[4];
    const float* ew2   = (const float*)d_in[5];
    const float* eb2   = (const float*)d_in[6];
    const float* cont  = (const float*)d_in[7];
    const float* gw    = (const float*)d_in[8];
    const float* gb    = (const float*)d_in[9];
    const float* wih   = (const float*)d_in[10];
    const float* whh   = (const float*)d_in[11];
    const float* bih   = (const float*)d_in[12];
    const float* bhh   = (const float*)d_in[13];
    const float* hw1   = (const float*)d_in[14];
    const float* hb1   = (const float*)d_in[15];
    const float* hw2   = (const float*)d_in[16];
    const float* hb2   = (const float*)d_in[17];
    float* out = (float*)d_out;

    cudaFuncSetAttribute(mega, cudaFuncAttributeMaxDynamicSharedMemorySize, 69632);

    int perSM = 0;
    cudaOccupancyMaxActiveBlocksPerMultiprocessor(&perSM, mega, 256, 69632);
    if (perSM < 1) perSM = 1;
    if (perSM > 3) perSM = 3;
    int dev = 0, nsm = 148;
    cudaGetDevice(&dev);
    cudaDeviceGetAttribute(&nsm, cudaDevAttrMultiProcessorCount, dev);
    int nblk = perSM * nsm;

    mega<<<nblk, 256, 69632>>>(tf, types, prev, ew1, eb1, ew2, eb2, cont,
                               gw, gb, wih, whh, bih, bhh,
                               hw1, hb1, hw2, hb2, out, nblk);
}